// round 15
// baseline (speedup 1.0000x reference)
#include <cuda_runtime.h>
#include <cuda_fp16.h>
#include <cstdint>

// ----------------------------------------------------------------------------
// FFT-domain block-circulant matmul.
//   K_T : build constant DFT / iDFT operand images (pre-swizzled)
//   K_W : W plane, complex-interleaved over k2=2i+{r,i}:  BWr [f][o][128]
//         (the Wi plane is derived in-register in K2: (wi,wr) = swap+neg of (wr,-wi))
//   K1  : X2[f][r] = half2(Xr,Xi)  (forward DFT GEMM, transposed epilogue)
//   K2  : Y2[f][r] = half2(Yr,Yi)  (W resident, 4 tiles, X dbl-buffered)
//   K3  : out = [Y2 rows] @ iDFT   (128-row tiles, dbl-buffered, 4 CTAs/SM)
// ----------------------------------------------------------------------------
#define TOKENS 4096
#define NBLK   64
#define BLK    64
#define NMAT   4
#define NFREQ  33
#define RROWS  (TOKENS * NBLK)      // 262144

static __device__ __half2 g_X2[(size_t)NFREQ * RROWS];
static __device__ __half2 g_Y2[(size_t)NFREQ * RROWS];
static __device__ __half g_WBr[(size_t)NFREQ * NBLK * 128];
static __device__ __half g_Bf_img[80 * 64];    // fwd DFT, swizzled image (10KB)
static __device__ __half g_Bi_img[64 * 88];    // iDFT, padded rows 176B (11KB)

// ----------------------------------------------------------------------------
// Helpers
// ----------------------------------------------------------------------------
__device__ __forceinline__ uint32_t h2u(__half2 v) {
    union { __half2 h; uint32_t u; } c;
    c.h = v;
    return c.u;
}

__device__ __forceinline__ uint32_t smem_u32(const void* p) {
    uint32_t a;
    asm("{ .reg .u64 t; cvta.to.shared.u64 t, %1; cvt.u32.u64 %0, t; }"
        : "=r"(a) : "l"(p));
    return a;
}

__device__ __forceinline__ void cp_async16(uint32_t dst, const void* src) {
    asm volatile("cp.async.cg.shared.global [%0], [%1], 16;\n"
                 :: "r"(dst), "l"(src));
}
__device__ __forceinline__ void cp_async4(uint32_t dst, const void* src) {
    asm volatile("cp.async.ca.shared.global [%0], [%1], 4;\n"
                 :: "r"(dst), "l"(src));
}
#define CP_COMMIT() asm volatile("cp.async.commit_group;\n" ::: "memory")
#define CP_WAIT0()  asm volatile("cp.async.wait_group 0;\n" ::: "memory")
#define CP_WAIT1()  asm volatile("cp.async.wait_group 1;\n" ::: "memory")

__device__ __forceinline__ void ldsm_x4(uint32_t* r, uint32_t addr) {
    asm volatile("ldmatrix.sync.aligned.m8n8.x4.shared.b16 {%0,%1,%2,%3}, [%4];"
                 : "=r"(r[0]), "=r"(r[1]), "=r"(r[2]), "=r"(r[3]) : "r"(addr));
}

__device__ __forceinline__ void mma16816(float* d, const uint32_t* a,
                                         const uint32_t* b) {
    asm volatile(
        "mma.sync.aligned.m16n8k16.row.col.f32.f16.f16.f32 "
        "{%0,%1,%2,%3}, {%4,%5,%6,%7}, {%8,%9}, {%0,%1,%2,%3};\n"
        : "+f"(d[0]), "+f"(d[1]), "+f"(d[2]), "+f"(d[3])
        : "r"(a[0]), "r"(a[1]), "r"(a[2]), "r"(a[3]), "r"(b[0]), "r"(b[1]));
}

// derive Wi-plane fragment register from Wr-plane register:
// br = (wr, -wi)  ->  bi = (wi, wr)   [swap halves, negate new lo]
__device__ __forceinline__ uint32_t wi_from_wr(uint32_t br) {
    uint32_t s;
    asm("prmt.b32 %0, %1, %1, 0x1032;" : "=r"(s) : "r"(br));
    return s ^ 0x00008000u;
}

// ----------------------------------------------------------------------------
// K_T: constant operand images (1 block, 128 threads)
// ----------------------------------------------------------------------------
__global__ void __launch_bounds__(128) k_tables() {
    __shared__ float ct[64], st[64];
    const int tid = threadIdx.x;
    if (tid < 64) { ct[tid] = cospif(tid / 32.f); st[tid] = sinpif(tid / 32.f); }
    __syncthreads();

    for (int idx = tid; idx < 80 * 64; idx += 128) {
        int f2 = idx >> 6, d = idx & 63;
        float v = 0.f;
        if (f2 < 33)      v = ct[(f2 * d) & 63];
        else if (f2 < 66) v = -st[((f2 - 33) * d) & 63];
        int pos = f2 * 64 + ((((d >> 3) ^ (f2 & 7)) << 3) | (d & 7));
        g_Bf_img[pos] = __float2half_rn(v);
    }
    for (int idx = tid; idx < 64 * 88; idx += 128) {
        int d = idx / 88, k = idx % 88;
        float v = 0.f;
        if (k < 66) {
            int f = k >> 1;
            float wf = (f == 0 || f == 32) ? (1.f / 64.f) : (2.f / 64.f);
            v = (k & 1) ? -wf * st[(f * d) & 63] : wf * ct[(f * d) & 63];
        }
        g_Bi_img[idx] = __float2half_rn(v);
    }
}

// ----------------------------------------------------------------------------
// K_W: weight FFT -> interleaved Wr plane.  One block per (o,i); 64 threads.
// ----------------------------------------------------------------------------
__global__ void __launch_bounds__(64) kw_fft(const float* __restrict__ p,
                                             const float* __restrict__ w) {
    __shared__ float cw[BLK];
    __shared__ float ct[64], st[64];
    const int oi = blockIdx.x;        // o*64+i
    const int o = oi >> 6, i = oi & 63;
    const int t = threadIdx.x;

    ct[t] = cospif(t / 32.f);
    st[t] = sinpif(t / 32.f);

    float acc = 0.f;
#pragma unroll
    for (int m = 0; m < NMAT; ++m)
        acc += w[m] * p[(size_t)m * (NBLK * NBLK * BLK) + (size_t)oi * BLK + t];
    cw[t] = acc;
    __syncthreads();

    if (t < NFREQ) {
        float wr = 0.f, wi = 0.f;
#pragma unroll
        for (int d = 0; d < BLK; ++d) {
            int k = (t * d) & 63;
            wr += cw[d] * ct[k];
            wi -= cw[d] * st[k];
        }
        const size_t base = ((size_t)t * NBLK + o) * 128 + 2 * i;
        g_WBr[base]     = __float2half_rn(wr);
        g_WBr[base + 1] = __float2half_rn(-wi);
    }
}

// ----------------------------------------------------------------------------
// K1: forward DFT GEMM.  M=262144 (r=t*64+i), N=66(->72), K=64.
// 128 threads, 128 rows/CTA.  (round-8 proven version, unchanged)
// ----------------------------------------------------------------------------
__global__ void __launch_bounds__(128) k1_dft(const float* __restrict__ x) {
    __shared__ __align__(128) char sm[26624];
    const uint32_t sb = smem_u32(sm);
    const int tid = threadIdx.x;
    const int wid = tid >> 5, lane = tid & 31;
    const int r0 = (int)blockIdx.x * 128;

#pragma unroll
    for (int it = 0; it < 5; ++it) {
        int chunk = tid + it * 128;
        cp_async16(sb + 16384 + chunk * 16, g_Bf_img + chunk * 8);
    }
    CP_COMMIT();

#pragma unroll
    for (int it = 0; it < 8; ++it) {
        int idx = tid + it * 128;
        int r = idx >> 3, c = idx & 7;
        const float4* src = reinterpret_cast<const float4*>(
            x + (size_t)(r0 + r) * 64 + c * 8);
        float4 v0 = src[0], v1 = src[1];
        union { __half2 h[4]; uint4 u; } pk;
        pk.h[0] = __floats2half2_rn(v0.x, v0.y);
        pk.h[1] = __floats2half2_rn(v0.z, v0.w);
        pk.h[2] = __floats2half2_rn(v1.x, v1.y);
        pk.h[3] = __floats2half2_rn(v1.z, v1.w);
        *reinterpret_cast<uint4*>(sm + r * 128 + ((c ^ (r & 7)) << 4)) = pk.u;
    }
    CP_WAIT0();
    __syncthreads();

    const int wm = wid * 32;
    float acc[2][9][4] = {};
#pragma unroll
    for (int kc = 0; kc < 4; ++kc) {
        uint32_t a[2][4], b[5][4];
#pragma unroll
        for (int mt = 0; mt < 2; ++mt) {
            int row = wm + mt * 16 + (lane & 15);
            int ch = kc * 2 + (lane >> 4);
            ldsm_x4(a[mt], sb + row * 128 + ((ch ^ (row & 7)) << 4));
        }
#pragma unroll
        for (int bt = 0; bt < 5; ++bt) {
            int row = bt * 16 + (lane >> 4) * 8 + (lane & 7);
            int ch = kc * 2 + ((lane & 15) >> 3);
            ldsm_x4(b[bt], sb + 16384 + row * 128 + ((ch ^ (row & 7)) << 4));
        }
#pragma unroll
        for (int mt = 0; mt < 2; ++mt)
#pragma unroll
            for (int nt = 0; nt < 9; ++nt)
                mma16816(acc[mt][nt], a[mt], &b[nt >> 1][(nt & 1) * 2]);
    }
    __syncthreads();

#pragma unroll
    for (int mt = 0; mt < 2; ++mt)
#pragma unroll
        for (int nt = 0; nt < 9; ++nt) {
            int row = wm + mt * 16 + (lane >> 2);
            int col = nt * 8 + (lane & 3) * 2;
            *reinterpret_cast<__half*>(sm + col * 256 + row * 2) =
                __float2half_rn(acc[mt][nt][0]);
            *reinterpret_cast<__half*>(sm + (col + 1) * 256 + row * 2) =
                __float2half_rn(acc[mt][nt][1]);
            *reinterpret_cast<__half*>(sm + col * 256 + (row + 8) * 2) =
                __float2half_rn(acc[mt][nt][2]);
            *reinterpret_cast<__half*>(sm + (col + 1) * 256 + (row + 8) * 2) =
                __float2half_rn(acc[mt][nt][3]);
        }
    __syncthreads();

#pragma unroll
    for (int f = 0; f < NFREQ; ++f) {
        __half lo = *reinterpret_cast<__half*>(sm + f * 256 + tid * 2);
        __half hi = *reinterpret_cast<__half*>(sm + (f + 33) * 256 + tid * 2);
        reinterpret_cast<uint32_t*>(g_X2)[(size_t)f * RROWS + r0 + tid] =
            h2u(__halves2half2(lo, hi));
    }
}

// ----------------------------------------------------------------------------
// K2: per-frequency GEMM, K=128 interleaved complex contraction.
// grid = 33*8; CTA = 256 thr; Wr plane resident; Wi fragments derived
// in-register (swap+neg).  4 token-tiles of 128, X double-buffered.
// smem: X0@0 (32KB), X1@32768, BWr@65536 (16KB) = 80KB.
// ----------------------------------------------------------------------------
__device__ __forceinline__ uint32_t sw256(int row, int ch) {
    return (uint32_t)(row * 256 + ((ch >> 3) << 7) + ((((ch & 7) ^ (row & 7))) << 4));
}

__global__ void __launch_bounds__(256, 2) k2_cgemm() {
    extern __shared__ __align__(128) char dsm[];
    const uint32_t sb = smem_u32(dsm);
    const int tid = threadIdx.x;
    const int wid = tid >> 5, lane = tid & 31;
    const int f = (int)blockIdx.x >> 3;
    const int g = (int)blockIdx.x & 7;

    const char* Xbase = reinterpret_cast<const char*>(g_X2) + (size_t)f * RROWS * 4;
    const __half* WrP = g_WBr + (size_t)f * NBLK * 128;

    // Wr plane resident (part of group 0)
#pragma unroll
    for (int it = 0; it < 4; ++it) {
        int idx = tid + it * 256;
        int r = idx >> 4, ch = idx & 15;
        cp_async16(sb + 65536 + sw256(r, ch), WrP + r * 128 + ch * 8);
    }

    auto loadX = [&](int j) {
        const char* Xs = Xbase + (size_t)(g * 4 + j) * 128 * 256;
        uint32_t xb = sb + (uint32_t)(j & 1) * 32768;
#pragma unroll
        for (int it = 0; it < 8; ++it) {
            int idx = tid + it * 256;
            int r = idx >> 4, ch = idx & 15;
            cp_async16(xb + sw256(r, ch), Xs + r * 256 + ch * 16);
        }
    };
    loadX(0); CP_COMMIT();      // G0 = W + X0
    loadX(1); CP_COMMIT();      // G1 = X1

    const int wm = (wid >> 1) * 32;
    const int wn = (wid & 1) * 32;

    for (int j = 0; j < 4; ++j) {
        CP_WAIT1();             // group j complete (W done at j=0)
        __syncthreads();

        const uint32_t xb = sb + (uint32_t)(j & 1) * 32768;
        float aR[2][4][4] = {}, aI[2][4][4] = {};

#pragma unroll
        for (int kc = 0; kc < 8; ++kc) {
            uint32_t a[2][4], br[2][4], bi[2][4];
#pragma unroll
            for (int mt = 0; mt < 2; ++mt) {
                int row = wm + mt * 16 + (lane & 15);
                int ch = kc * 2 + (lane >> 4);
                ldsm_x4(a[mt], xb + sw256(row, ch));
            }
#pragma unroll
            for (int bt = 0; bt < 2; ++bt) {
                int row = wn + bt * 16 + (lane >> 4) * 8 + (lane & 7);
                int ch = kc * 2 + ((lane & 15) >> 3);
                ldsm_x4(br[bt], sb + 65536 + sw256(row, ch));
#pragma unroll
                for (int q = 0; q < 4; ++q)
                    bi[bt][q] = wi_from_wr(br[bt][q]);
            }
#pragma unroll
            for (int mt = 0; mt < 2; ++mt)
#pragma unroll
                for (int nt = 0; nt < 4; ++nt) {
                    mma16816(aR[mt][nt], a[mt], &br[nt >> 1][(nt & 1) * 2]);
                    mma16816(aI[mt][nt], a[mt], &bi[nt >> 1][(nt & 1) * 2]);
                }
        }

        uint32_t* Y = reinterpret_cast<uint32_t*>(g_Y2) +
                      (size_t)f * RROWS + (size_t)(g * 4 + j) * 128 * 64;
#pragma unroll
        for (int mt = 0; mt < 2; ++mt)
#pragma unroll
            for (int nt = 0; nt < 4; ++nt) {
                int row = wm + mt * 16 + (lane >> 2);
                int col = wn + nt * 8 + (lane & 3) * 2;
                Y[(size_t)row * 64 + col] =
                    h2u(__floats2half2_rn(aR[mt][nt][0], aI[mt][nt][0]));
                Y[(size_t)row * 64 + col + 1] =
                    h2u(__floats2half2_rn(aR[mt][nt][1], aI[mt][nt][1]));
                Y[(size_t)(row + 8) * 64 + col] =
                    h2u(__floats2half2_rn(aR[mt][nt][2], aI[mt][nt][2]));
                Y[(size_t)(row + 8) * 64 + col + 1] =
                    h2u(__floats2half2_rn(aR[mt][nt][3], aI[mt][nt][3]));
            }

        __syncthreads();        // everyone done reading buffer (j&1)
        if (j < 2) loadX(j + 2);
        CP_COMMIT();            // empty group ok for j >= 2
    }
}

// ----------------------------------------------------------------------------
// K3: inverse DFT GEMM.  M=262144 (r=t*64+o), N=64, K=66->80.
// 128 threads, 2 tiles of 128 rows per CTA, A double-buffered; B resident.
// smem dyn 56320: A0@0 (22528), A1@22528, B@45056 (11264). 4 CTAs/SM (220KB).
// ----------------------------------------------------------------------------
__global__ void __launch_bounds__(128, 4) k3_idft(float* __restrict__ out) {
    extern __shared__ __align__(128) char dsm[];
    const uint32_t sb = smem_u32(dsm);
    const uint32_t sbB = sb + 45056;
    const int tid = threadIdx.x;
    const int wid = tid >> 5, lane = tid & 31;
    const int g = (int)blockIdx.x;

    // B image resident (group 0): 704 x 16B
#pragma unroll
    for (int it = 0; it < 6; ++it) {
        int idx = tid + it * 128;
        if (idx < 704) cp_async16(sbB + idx * 16, g_Bi_img + idx * 8);
    }

    auto loadA = [&](int j) {
        const uint32_t ab = sb + (uint32_t)j * 22528;
        char* abp = dsm + (size_t)j * 22528;
        const size_t r0 = (size_t)(g * 2 + j) * 128;
        const uint32_t arow = ab + tid * 176;
#pragma unroll
        for (int q = 0; q < 7; ++q)
            *reinterpret_cast<uint32_t*>(abp + tid * 176 + 132 + q * 4) = 0u;
        const char* ysrc = reinterpret_cast<const char*>(g_Y2) + (r0 + tid) * 4;
#pragma unroll
        for (int fq = 0; fq < NFREQ; ++fq)
            cp_async4(arow + fq * 4, ysrc + (size_t)fq * RROWS * 4);
    };
    loadA(0); CP_COMMIT();      // G0 = B + A0
    loadA(1); CP_COMMIT();      // G1 = A1

    const int wm = wid * 32;

#pragma unroll
    for (int j = 0; j < 2; ++j) {
        if (j == 0) CP_WAIT1(); else CP_WAIT0();
        __syncthreads();

        const uint32_t ab = sb + (uint32_t)j * 22528;
        const int r0 = (g * 2 + j) * 128;
        float acc[2][8][4] = {};

#pragma unroll
        for (int kc = 0; kc < 5; ++kc) {
            uint32_t a[2][4], b[4][4];
#pragma unroll
            for (int mt = 0; mt < 2; ++mt) {
                int row = wm + mt * 16 + (lane & 15);
                int ch = kc * 2 + (lane >> 4);
                ldsm_x4(a[mt], ab + row * 176 + ch * 16);
            }
#pragma unroll
            for (int bt = 0; bt < 4; ++bt) {
                int row = bt * 16 + (lane >> 4) * 8 + (lane & 7);
                int ch = kc * 2 + ((lane & 15) >> 3);
                ldsm_x4(b[bt], sbB + row * 176 + ch * 16);
            }
#pragma unroll
            for (int mt = 0; mt < 2; ++mt)
#pragma unroll
                for (int nt = 0; nt < 8; ++nt)
                    mma16816(acc[mt][nt], a[mt], &b[nt >> 1][(nt & 1) * 2]);
        }

#pragma unroll
        for (int mt = 0; mt < 2; ++mt)
#pragma unroll
            for (int nt = 0; nt < 8; ++nt) {
                int row = r0 + wm + mt * 16 + (lane >> 2);
                int col = nt * 8 + (lane & 3) * 2;
                *reinterpret_cast<float2*>(out + (size_t)row * 64 + col) =
                    make_float2(acc[mt][nt][0], acc[mt][nt][1]);
                *reinterpret_cast<float2*>(out + (size_t)(row + 8) * 64 + col) =
                    make_float2(acc[mt][nt][2], acc[mt][nt][3]);
            }
    }
}

// ----------------------------------------------------------------------------
// Host entry
// ----------------------------------------------------------------------------
extern "C" void kernel_launch(void* const* d_in, const int* in_sizes, int n_in,
                              void* d_out, int out_size) {
    const float* x       = (const float*)d_in[0];
    const float* params  = (const float*)d_in[1];
    const float* weights = (const float*)d_in[2];
    float* out = (float*)d_out;

    k_tables<<<1, 128>>>();
    kw_fft<<<NBLK * NBLK, 64>>>(params, weights);
    k1_dft<<<RROWS / 128, 128>>>(x);

    cudaFuncSetAttribute(k2_cgemm, cudaFuncAttributeMaxDynamicSharedMemorySize,
                         81920);
    k2_cgemm<<<NFREQ * 8, 256, 81920>>>();

    cudaFuncSetAttribute(k3_idft, cudaFuncAttributeMaxDynamicSharedMemorySize,
                         56320);
    k3_idft<<<RROWS / 256, 128, 56320>>>(out);
}

// round 17
// speedup vs baseline: 1.4837x; 1.4837x over previous
#include <cuda_runtime.h>
#include <cuda_fp16.h>
#include <cstdint>

// ----------------------------------------------------------------------------
// FFT-domain block-circulant matmul.  (round-14 proven config, kw+tables fused)
//   K_W : fused — blocks 0..4095 weight-FFT planes; block 4096 DFT images
//   K1  : X2[f][r] = half2(Xr,Xi)  (forward DFT GEMM, transposed epilogue)
//   K2  : Y2[f][r] = half2(Yr,Yi)  (W resident, 4 tiles, X dbl-buffered)
//   K3  : out = [Y2 rows] @ iDFT   (128-row CTAs, 4 CTAs/SM, static smem)
// ----------------------------------------------------------------------------
#define TOKENS 4096
#define NBLK   64
#define BLK    64
#define NMAT   4
#define NFREQ  33
#define RROWS  (TOKENS * NBLK)      // 262144

static __device__ __half2 g_X2[(size_t)NFREQ * RROWS];
static __device__ __half2 g_Y2[(size_t)NFREQ * RROWS];
static __device__ __half g_WBr[(size_t)NFREQ * NBLK * 128];
static __device__ __half g_WBi[(size_t)NFREQ * NBLK * 128];
static __device__ __half g_Bf_img[80 * 64];    // fwd DFT, swizzled image (10KB)
static __device__ __half g_Bi_img[64 * 88];    // iDFT, padded rows 176B (11KB)

// ----------------------------------------------------------------------------
// Helpers
// ----------------------------------------------------------------------------
__device__ __forceinline__ uint32_t h2u(__half2 v) {
    union { __half2 h; uint32_t u; } c;
    c.h = v;
    return c.u;
}

__device__ __forceinline__ uint32_t smem_u32(const void* p) {
    uint32_t a;
    asm("{ .reg .u64 t; cvta.to.shared.u64 t, %1; cvt.u32.u64 %0, t; }"
        : "=r"(a) : "l"(p));
    return a;
}

__device__ __forceinline__ void cp_async16(uint32_t dst, const void* src) {
    asm volatile("cp.async.cg.shared.global [%0], [%1], 16;\n"
                 :: "r"(dst), "l"(src));
}
__device__ __forceinline__ void cp_async4(uint32_t dst, const void* src) {
    asm volatile("cp.async.ca.shared.global [%0], [%1], 4;\n"
                 :: "r"(dst), "l"(src));
}
#define CP_COMMIT() asm volatile("cp.async.commit_group;\n" ::: "memory")
#define CP_WAIT0()  asm volatile("cp.async.wait_group 0;\n" ::: "memory")
#define CP_WAIT1()  asm volatile("cp.async.wait_group 1;\n" ::: "memory")

__device__ __forceinline__ void ldsm_x4(uint32_t* r, uint32_t addr) {
    asm volatile("ldmatrix.sync.aligned.m8n8.x4.shared.b16 {%0,%1,%2,%3}, [%4];"
                 : "=r"(r[0]), "=r"(r[1]), "=r"(r[2]), "=r"(r[3]) : "r"(addr));
}

__device__ __forceinline__ void mma16816(float* d, const uint32_t* a,
                                         const uint32_t* b) {
    asm volatile(
        "mma.sync.aligned.m16n8k16.row.col.f32.f16.f16.f32 "
        "{%0,%1,%2,%3}, {%4,%5,%6,%7}, {%8,%9}, {%0,%1,%2,%3};\n"
        : "+f"(d[0]), "+f"(d[1]), "+f"(d[2]), "+f"(d[3])
        : "r"(a[0]), "r"(a[1]), "r"(a[2]), "r"(a[3]), "r"(b[0]), "r"(b[1]));
}

// ----------------------------------------------------------------------------
// K_W fused: blocks 0..4095 = weight FFT (one (o,i) pair each, 64 threads);
// block 4096 = constant DFT/iDFT operand images.
// ----------------------------------------------------------------------------
__global__ void __launch_bounds__(64) kw_fused(const float* __restrict__ p,
                                               const float* __restrict__ w) {
    __shared__ float cw[BLK];
    __shared__ float ct[64], st[64];
    const int t = threadIdx.x;

    ct[t] = cospif(t / 32.f);
    st[t] = sinpif(t / 32.f);

    if (blockIdx.x == NBLK * NBLK) {
        // --- constant operand images ---
        __syncthreads();
        for (int idx = t; idx < 80 * 64; idx += 64) {
            int f2 = idx >> 6, d = idx & 63;
            float v = 0.f;
            if (f2 < 33)      v = ct[(f2 * d) & 63];
            else if (f2 < 66) v = -st[((f2 - 33) * d) & 63];
            int pos = f2 * 64 + ((((d >> 3) ^ (f2 & 7)) << 3) | (d & 7));
            g_Bf_img[pos] = __float2half_rn(v);
        }
        for (int idx = t; idx < 64 * 88; idx += 64) {
            int d = idx / 88, k = idx % 88;
            float v = 0.f;
            if (k < 66) {
                int f = k >> 1;
                float wf = (f == 0 || f == 32) ? (1.f / 64.f) : (2.f / 64.f);
                v = (k & 1) ? -wf * st[(f * d) & 63] : wf * ct[(f * d) & 63];
            }
            g_Bi_img[idx] = __float2half_rn(v);
        }
        return;
    }

    // --- weight FFT for this (o,i) pair ---
    const int oi = blockIdx.x;        // o*64+i
    const int o = oi >> 6, i = oi & 63;

    float acc = 0.f;
#pragma unroll
    for (int m = 0; m < NMAT; ++m)
        acc += w[m] * p[(size_t)m * (NBLK * NBLK * BLK) + (size_t)oi * BLK + t];
    cw[t] = acc;
    __syncthreads();

    if (t < NFREQ) {
        float wr = 0.f, wi = 0.f;
#pragma unroll
        for (int d = 0; d < BLK; ++d) {
            int k = (t * d) & 63;
            wr += cw[d] * ct[k];
            wi -= cw[d] * st[k];
        }
        const size_t base = ((size_t)t * NBLK + o) * 128 + 2 * i;
        g_WBr[base]     = __float2half_rn(wr);
        g_WBr[base + 1] = __float2half_rn(-wi);
        g_WBi[base]     = __float2half_rn(wi);
        g_WBi[base + 1] = __float2half_rn(wr);
    }
}

// ----------------------------------------------------------------------------
// K1: forward DFT GEMM.  M=262144 (r=t*64+i), N=66(->72), K=64.
// 128 threads, 128 rows/CTA.  (round-8 proven version, unchanged)
// ----------------------------------------------------------------------------
__global__ void __launch_bounds__(128) k1_dft(const float* __restrict__ x) {
    __shared__ __align__(128) char sm[26624];
    const uint32_t sb = smem_u32(sm);
    const int tid = threadIdx.x;
    const int wid = tid >> 5, lane = tid & 31;
    const int r0 = (int)blockIdx.x * 128;

#pragma unroll
    for (int it = 0; it < 5; ++it) {
        int chunk = tid + it * 128;
        cp_async16(sb + 16384 + chunk * 16, g_Bf_img + chunk * 8);
    }
    CP_COMMIT();

#pragma unroll
    for (int it = 0; it < 8; ++it) {
        int idx = tid + it * 128;
        int r = idx >> 3, c = idx & 7;
        const float4* src = reinterpret_cast<const float4*>(
            x + (size_t)(r0 + r) * 64 + c * 8);
        float4 v0 = src[0], v1 = src[1];
        union { __half2 h[4]; uint4 u; } pk;
        pk.h[0] = __floats2half2_rn(v0.x, v0.y);
        pk.h[1] = __floats2half2_rn(v0.z, v0.w);
        pk.h[2] = __floats2half2_rn(v1.x, v1.y);
        pk.h[3] = __floats2half2_rn(v1.z, v1.w);
        *reinterpret_cast<uint4*>(sm + r * 128 + ((c ^ (r & 7)) << 4)) = pk.u;
    }
    CP_WAIT0();
    __syncthreads();

    const int wm = wid * 32;
    float acc[2][9][4] = {};
#pragma unroll
    for (int kc = 0; kc < 4; ++kc) {
        uint32_t a[2][4], b[5][4];
#pragma unroll
        for (int mt = 0; mt < 2; ++mt) {
            int row = wm + mt * 16 + (lane & 15);
            int ch = kc * 2 + (lane >> 4);
            ldsm_x4(a[mt], sb + row * 128 + ((ch ^ (row & 7)) << 4));
        }
#pragma unroll
        for (int bt = 0; bt < 5; ++bt) {
            int row = bt * 16 + (lane >> 4) * 8 + (lane & 7);
            int ch = kc * 2 + ((lane & 15) >> 3);
            ldsm_x4(b[bt], sb + 16384 + row * 128 + ((ch ^ (row & 7)) << 4));
        }
#pragma unroll
        for (int mt = 0; mt < 2; ++mt)
#pragma unroll
            for (int nt = 0; nt < 9; ++nt)
                mma16816(acc[mt][nt], a[mt], &b[nt >> 1][(nt & 1) * 2]);
    }
    __syncthreads();

#pragma unroll
    for (int mt = 0; mt < 2; ++mt)
#pragma unroll
        for (int nt = 0; nt < 9; ++nt) {
            int row = wm + mt * 16 + (lane >> 2);
            int col = nt * 8 + (lane & 3) * 2;
            *reinterpret_cast<__half*>(sm + col * 256 + row * 2) =
                __float2half_rn(acc[mt][nt][0]);
            *reinterpret_cast<__half*>(sm + (col + 1) * 256 + row * 2) =
                __float2half_rn(acc[mt][nt][1]);
            *reinterpret_cast<__half*>(sm + col * 256 + (row + 8) * 2) =
                __float2half_rn(acc[mt][nt][2]);
            *reinterpret_cast<__half*>(sm + (col + 1) * 256 + (row + 8) * 2) =
                __float2half_rn(acc[mt][nt][3]);
        }
    __syncthreads();

#pragma unroll
    for (int f = 0; f < NFREQ; ++f) {
        __half lo = *reinterpret_cast<__half*>(sm + f * 256 + tid * 2);
        __half hi = *reinterpret_cast<__half*>(sm + (f + 33) * 256 + tid * 2);
        reinterpret_cast<uint32_t*>(g_X2)[(size_t)f * RROWS + r0 + tid] =
            h2u(__halves2half2(lo, hi));
    }
}

// ----------------------------------------------------------------------------
// K2: per-frequency GEMM, K=128 interleaved complex contraction.
// grid = 33*8; CTA = 256 thr; W planes resident; 4 token-tiles of 128,
// X double-buffered via cp.async groups.  (round-12/14 proven: 24.1us)
// smem: X0@0 (32KB), X1@32768, BWr@65536 (16KB), BWi@81920 (16KB) = 96KB.
// ----------------------------------------------------------------------------
__device__ __forceinline__ uint32_t sw256(int row, int ch) {
    return (uint32_t)(row * 256 + ((ch >> 3) << 7) + ((((ch & 7) ^ (row & 7))) << 4));
}

__global__ void __launch_bounds__(256, 2) k2_cgemm() {
    extern __shared__ __align__(128) char dsm[];
    const uint32_t sb = smem_u32(dsm);
    const int tid = threadIdx.x;
    const int wid = tid >> 5, lane = tid & 31;
    const int f = (int)blockIdx.x >> 3;
    const int g = (int)blockIdx.x & 7;

    const char* Xbase = reinterpret_cast<const char*>(g_X2) + (size_t)f * RROWS * 4;
    const __half* WrP = g_WBr + (size_t)f * NBLK * 128;
    const __half* WiP = g_WBi + (size_t)f * NBLK * 128;

    // W planes resident (part of group 0)
#pragma unroll
    for (int it = 0; it < 4; ++it) {
        int idx = tid + it * 256;
        int r = idx >> 4, ch = idx & 15;
        cp_async16(sb + 65536 + sw256(r, ch), WrP + r * 128 + ch * 8);
        cp_async16(sb + 81920 + sw256(r, ch), WiP + r * 128 + ch * 8);
    }

    auto loadX = [&](int j) {
        const char* Xs = Xbase + (size_t)(g * 4 + j) * 128 * 256;
        uint32_t xb = sb + (uint32_t)(j & 1) * 32768;
#pragma unroll
        for (int it = 0; it < 8; ++it) {
            int idx = tid + it * 256;
            int r = idx >> 4, ch = idx & 15;
            cp_async16(xb + sw256(r, ch), Xs + r * 256 + ch * 16);
        }
    };
    loadX(0); CP_COMMIT();      // G0 = W + X0
    loadX(1); CP_COMMIT();      // G1 = X1

    const int wm = (wid >> 1) * 32;
    const int wn = (wid & 1) * 32;

    for (int j = 0; j < 4; ++j) {
        CP_WAIT1();             // group j complete (W done at j=0)
        __syncthreads();

        const uint32_t xb = sb + (uint32_t)(j & 1) * 32768;
        float aR[2][4][4] = {}, aI[2][4][4] = {};

#pragma unroll
        for (int kc = 0; kc < 8; ++kc) {
            uint32_t a[2][4], br[2][4], bi[2][4];
#pragma unroll
            for (int mt = 0; mt < 2; ++mt) {
                int row = wm + mt * 16 + (lane & 15);
                int ch = kc * 2 + (lane >> 4);
                ldsm_x4(a[mt], xb + sw256(row, ch));
            }
#pragma unroll
            for (int bt = 0; bt < 2; ++bt) {
                int row = wn + bt * 16 + (lane >> 4) * 8 + (lane & 7);
                int ch = kc * 2 + ((lane & 15) >> 3);
                ldsm_x4(br[bt], sb + 65536 + sw256(row, ch));
                ldsm_x4(bi[bt], sb + 81920 + sw256(row, ch));
            }
#pragma unroll
            for (int mt = 0; mt < 2; ++mt)
#pragma unroll
                for (int nt = 0; nt < 4; ++nt) {
                    mma16816(aR[mt][nt], a[mt], &br[nt >> 1][(nt & 1) * 2]);
                    mma16816(aI[mt][nt], a[mt], &bi[nt >> 1][(nt & 1) * 2]);
                }
        }

        uint32_t* Y = reinterpret_cast<uint32_t*>(g_Y2) +
                      (size_t)f * RROWS + (size_t)(g * 4 + j) * 128 * 64;
#pragma unroll
        for (int mt = 0; mt < 2; ++mt)
#pragma unroll
            for (int nt = 0; nt < 4; ++nt) {
                int row = wm + mt * 16 + (lane >> 2);
                int col = wn + nt * 8 + (lane & 3) * 2;
                Y[(size_t)row * 64 + col] =
                    h2u(__floats2half2_rn(aR[mt][nt][0], aI[mt][nt][0]));
                Y[(size_t)row * 64 + col + 1] =
                    h2u(__floats2half2_rn(aR[mt][nt][1], aI[mt][nt][1]));
                Y[(size_t)(row + 8) * 64 + col] =
                    h2u(__floats2half2_rn(aR[mt][nt][2], aI[mt][nt][2]));
                Y[(size_t)(row + 8) * 64 + col + 1] =
                    h2u(__floats2half2_rn(aR[mt][nt][3], aI[mt][nt][3]));
            }

        __syncthreads();        // everyone done reading buffer (j&1)
        if (j < 2) loadX(j + 2);
        CP_COMMIT();            // empty group ok for j >= 2
    }
}

// ----------------------------------------------------------------------------
// K3: inverse DFT GEMM.  M=262144 (r=t*64+o), N=64, K=66->80.
// 128-row CTAs, 128 threads, static smem 33.8KB -> 4 CTAs/SM.
// (round-14 proven version, unchanged)
// ----------------------------------------------------------------------------
__global__ void __launch_bounds__(128, 4) k3_idft(float* __restrict__ out) {
    __shared__ __align__(128) char sm[33792];
    const uint32_t sb = smem_u32(sm);
    const uint32_t sbB = sb + 22528;
    const int tid = threadIdx.x;
    const int wid = tid >> 5, lane = tid & 31;
    const int r0 = (int)blockIdx.x * 128;

    // B image: 704 x 16B
#pragma unroll
    for (int it = 0; it < 6; ++it) {
        int idx = tid + it * 128;
        if (idx < 704) cp_async16(sbB + idx * 16, g_Bi_img + idx * 8);
    }
    // A: one row per thread; zero pad then 33 x 4B cp.async
    {
        const uint32_t arow = sb + tid * 176;
#pragma unroll
        for (int q = 0; q < 7; ++q)
            *reinterpret_cast<uint32_t*>(sm + tid * 176 + 132 + q * 4) = 0u;
        const char* ysrc = reinterpret_cast<const char*>(g_Y2) +
                           ((size_t)r0 + tid) * 4;
#pragma unroll
        for (int fq = 0; fq < NFREQ; ++fq)
            cp_async4(arow + fq * 4, ysrc + (size_t)fq * RROWS * 4);
    }
    CP_COMMIT();
    CP_WAIT0();
    __syncthreads();

    const int wm = wid * 32;
    float acc[2][8][4] = {};
#pragma unroll
    for (int kc = 0; kc < 5; ++kc) {
        uint32_t a[2][4], b[4][4];
#pragma unroll
        for (int mt = 0; mt < 2; ++mt) {
            int row = wm + mt * 16 + (lane & 15);
            int ch = kc * 2 + (lane >> 4);
            ldsm_x4(a[mt], sb + row * 176 + ch * 16);
        }
#pragma unroll
        for (int bt = 0; bt < 4; ++bt) {
            int row = bt * 16 + (lane >> 4) * 8 + (lane & 7);
            int ch = kc * 2 + ((lane & 15) >> 3);
            ldsm_x4(b[bt], sbB + row * 176 + ch * 16);
        }
#pragma unroll
        for (int mt = 0; mt < 2; ++mt)
#pragma unroll
            for (int nt = 0; nt < 8; ++nt)
                mma16816(acc[mt][nt], a[mt], &b[nt >> 1][(nt & 1) * 2]);
    }

#pragma unroll
    for (int mt = 0; mt < 2; ++mt)
#pragma unroll
        for (int nt = 0; nt < 8; ++nt) {
            int row = r0 + wm + mt * 16 + (lane >> 2);
            int col = nt * 8 + (lane & 3) * 2;
            *reinterpret_cast<float2*>(out + (size_t)row * 64 + col) =
                make_float2(acc[mt][nt][0], acc[mt][nt][1]);
            *reinterpret_cast<float2*>(out + (size_t)(row + 8) * 64 + col) =
                make_float2(acc[mt][nt][2], acc[mt][nt][3]);
        }
}

// ----------------------------------------------------------------------------
// Host entry
// ----------------------------------------------------------------------------
extern "C" void kernel_launch(void* const* d_in, const int* in_sizes, int n_in,
                              void* d_out, int out_size) {
    const float* x       = (const float*)d_in[0];
    const float* params  = (const float*)d_in[1];
    const float* weights = (const float*)d_in[2];
    float* out = (float*)d_out;

    kw_fused<<<NBLK * NBLK + 1, 64>>>(params, weights);
    k1_dft<<<RROWS / 128, 128>>>(x);

    cudaFuncSetAttribute(k2_cgemm, cudaFuncAttributeMaxDynamicSharedMemorySize,
                         98304);
    k2_cgemm<<<NFREQ * 8, 256, 98304>>>();

    k3_idft<<<RROWS / 128, 128>>>(out);
}